// round 4
// baseline (speedup 1.0000x reference)
#include <cuda_runtime.h>

// SparseSphereConv: BS=4, C_IN=C_OUT=32, V=40962, K=9
// out[b,o,v] = mask[b,v] * ( bias[o] + sum_{c,k} (sum_{k'} x[b,c,idx[v,k']] * itp[v,k',k]) * w[o,c,k] )
// mask[b,v] = any_{c,k'} ( x[b,c,idx[v,k']] != 0 )

#define V_TOT 40962
#define NBS   4
#define NCI   32
#define NCO   32
#define KNB   9
#define NROWS 128   // NBS * NCI

// Scratch: x transposed to [V][128] with row index r = b*32 + c  (21 MB, fits L2)
static __device__ float g_xt[(size_t)V_TOT * NROWS];

// ---------------------------------------------------------------------------
// Kernel 1: transpose x [128 rows (b*32+c), V cols] -> xt [V][128]
// Classic 32x32 tiled transpose, coalesced both directions.
// ---------------------------------------------------------------------------
__global__ void transpose_kernel(const float* __restrict__ x) {
    __shared__ float sh[32][33];
    const int n0 = blockIdx.x * 32;
    const int r0 = blockIdx.y * 32;
    const int tx = threadIdx.x, ty = threadIdx.y;
#pragma unroll
    for (int i = 0; i < 4; i++) {
        const int n = n0 + tx;
        const int r = r0 + ty + 8 * i;
        sh[ty + 8 * i][tx] = (n < V_TOT) ? x[(size_t)r * V_TOT + n] : 0.0f;
    }
    __syncthreads();
#pragma unroll
    for (int i = 0; i < 4; i++) {
        const int n = n0 + ty + 8 * i;
        if (n < V_TOT) g_xt[(size_t)n * NROWS + r0 + tx] = sh[tx][ty + 8 * i];
    }
}

// ---------------------------------------------------------------------------
// Kernel 2: fused gather + interp + conv + mask. 256 threads, 2 vertices/iter.
//
// Interp mapping : thread t -> (vv = t>>7, rr = t&127), b = rr>>5, c = rr&31.
//                  Gather of xt[idx*128 + rr] is 128B-coalesced per warp.
//                  Warp spans all 32 c for one (vv,b) -> ballot gives the mask.
// Conv mapping   : warp w = c-group (4 channels), lane = o. W slice (36 floats)
//                  is register-resident; all conv LDS are same-address
//                  broadcasts (1 cyc). Partials over the 8 c-groups reduced
//                  through shared memory.
// ---------------------------------------------------------------------------
__global__ __launch_bounds__(256, 2)
void sphere_kernel(const int*   __restrict__ nbr,
                   const float* __restrict__ itp,
                   const float* __restrict__ conv_w,
                   const float* __restrict__ conv_b,
                   float*       __restrict__ out)
{
    __shared__ int                    s_idx[2][KNB];
    __shared__ __align__(16) float    s_itp[2][KNB][12];     // k-rows padded to 12 (zeros)
    __shared__ __align__(16) float    s_f[2][NBS][NCI][12];  // interp results, k padded
    __shared__ float                  s_red[8][2][NBS][NCO]; // per-cgroup conv partials
    __shared__ int                    s_nz[2][NBS];

    const int t    = threadIdx.x;
    const int lane = t & 31;
    const int wid  = t >> 5;

    // --- conv-stage identity: (c-group, output channel) ---
    const int o  = lane;
    const int cg = wid;

    // W slice permanently in registers: w[o][cg*4+ci][k]
    float Wreg[4][KNB];
#pragma unroll
    for (int ci = 0; ci < 4; ci++)
#pragma unroll
        for (int k = 0; k < KNB; k++)
            Wreg[ci][k] = conv_w[((size_t)o * NCI + (cg * 4 + ci)) * KNB + k];

    const float bias = conv_b[lane];

    // --- interp-stage identity: (vertex-half, row) ---
    const int vv = t >> 7;       // which of the 2 vertices this iteration
    const int rr = t & 127;      // row = b*32 + c
    const int bI = rr >> 5;
    const int cI = rr & 31;

    const int NPAIR = V_TOT / 2; // 20481, exact

    for (int p = blockIdx.x; p < NPAIR; p += gridDim.x) {
        const int v0 = p * 2;

        // ---- stage 0: fill per-vertex metadata ----
        if (t < 2 * KNB) {
            // (v0+vvq)*9 + k == v0*9 + t
            s_idx[t / KNB][t % KNB] = nbr[v0 * KNB + t];
        }
        if (t < 216) {
            const int vvq = t / 108;
            const int e   = t - vvq * 108;
            const int k   = e / 12;
            const int j   = e - k * 12;
            s_itp[vvq][k][j] =
                (j < KNB) ? itp[(size_t)(v0 + vvq) * (KNB * KNB) + k * KNB + j] : 0.0f;
        }
        __syncthreads();  // A

        // ---- stage 1: gather (coalesced, L2-resident) + mask + interp ----
        float g[KNB];
        bool nz = false;
        const float* xb = g_xt + rr;
#pragma unroll
        for (int k = 0; k < KNB; k++) {
            g[k] = __ldg(xb + (size_t)s_idx[vv][k] * NROWS);
            nz |= (g[k] != 0.0f);
        }
        // warp = all 32 c for fixed (vv,b): ballot across c; OR over k already in nz
        const unsigned any_nz = __ballot_sync(0xFFFFFFFFu, nz);
        if (lane == 0) s_nz[vv][bI] = (any_nz != 0u) ? 1 : 0;

        float f[KNB];
#pragma unroll
        for (int j = 0; j < KNB; j++) f[j] = 0.0f;
#pragma unroll
        for (int k = 0; k < KNB; k++) {
            const float  gk = g[k];
            const float4 ia = *(const float4*)&s_itp[vv][k][0];
            const float4 ib = *(const float4*)&s_itp[vv][k][4];
            const float  ic = s_itp[vv][k][8];
            f[0] = fmaf(gk, ia.x, f[0]);
            f[1] = fmaf(gk, ia.y, f[1]);
            f[2] = fmaf(gk, ia.z, f[2]);
            f[3] = fmaf(gk, ia.w, f[3]);
            f[4] = fmaf(gk, ib.x, f[4]);
            f[5] = fmaf(gk, ib.y, f[5]);
            f[6] = fmaf(gk, ib.z, f[6]);
            f[7] = fmaf(gk, ib.w, f[7]);
            f[8] = fmaf(gk, ic,   f[8]);
        }
        float* frow = &s_f[vv][bI][cI][0];
        *(float4*)(frow)     = make_float4(f[0], f[1], f[2], f[3]);
        *(float4*)(frow + 4) = make_float4(f[4], f[5], f[6], f[7]);
        frow[8] = f[8];
        __syncthreads();  // B

        // ---- stage 2: conv, W in registers, interp via broadcast LDS ----
        float acc[2][NBS];
#pragma unroll
        for (int q = 0; q < 2; q++)
#pragma unroll
            for (int b = 0; b < NBS; b++) acc[q][b] = 0.0f;

#pragma unroll
        for (int q = 0; q < 2; q++) {
#pragma unroll
            for (int b = 0; b < NBS; b++) {
                float s = 0.0f;
#pragma unroll
                for (int ci = 0; ci < 4; ci++) {
                    const float* fr = &s_f[q][b][cg * 4 + ci][0];
                    const float4 fa = *(const float4*)(fr);
                    const float4 fb = *(const float4*)(fr + 4);
                    const float  fc = fr[8];
                    s = fmaf(fa.x, Wreg[ci][0], s);
                    s = fmaf(fa.y, Wreg[ci][1], s);
                    s = fmaf(fa.z, Wreg[ci][2], s);
                    s = fmaf(fa.w, Wreg[ci][3], s);
                    s = fmaf(fb.x, Wreg[ci][4], s);
                    s = fmaf(fb.y, Wreg[ci][5], s);
                    s = fmaf(fb.z, Wreg[ci][6], s);
                    s = fmaf(fb.w, Wreg[ci][7], s);
                    s = fmaf(fc,   Wreg[ci][8], s);
                }
                acc[q][b] = s;
            }
        }
#pragma unroll
        for (int q = 0; q < 2; q++)
#pragma unroll
            for (int b = 0; b < NBS; b++)
                s_red[cg][q][b][o] = acc[q][b];
        __syncthreads();  // C

        // ---- stage 3: reduce over the 8 c-groups, apply bias & mask, store ----
        {
            const int q  = t >> 7;
            const int b  = (t >> 5) & 3;
            const int oo = t & 31;
            float s = 0.0f;
#pragma unroll
            for (int w8 = 0; w8 < 8; w8++) s += s_red[w8][q][b][oo];
            s = (s + bias) * (float)s_nz[q][b];
            out[((size_t)b * NCO + oo) * V_TOT + (v0 + q)] = s;
        }
        // No trailing barrier needed: next-iter writes touch s_idx/s_itp (disjoint
        // from s_red/s_nz read here) before sync A, and s_nz/s_f writes occur
        // only after sync A, by which point all stage-3 reads have completed.
    }
}

extern "C" void kernel_launch(void* const* d_in, const int* in_sizes, int n_in,
                              void* d_out, int out_size) {
    (void)in_sizes; (void)n_in; (void)out_size;
    const float* x      = (const float*)d_in[0];
    const int*   nbr    = (const int*)  d_in[1];
    const float* itp    = (const float*)d_in[2];
    const float* conv_w = (const float*)d_in[3];
    const float* conv_b = (const float*)d_in[4];
    float*       out    = (float*)d_out;

    dim3 tb(32, 8);
    dim3 tg((V_TOT + 31) / 32, NROWS / 32);
    transpose_kernel<<<tg, tb>>>(x);

    sphere_kernel<<<888, 256>>>(nbr, itp, conv_w, conv_b, out);
}

// round 7
// speedup vs baseline: 1.1242x; 1.1242x over previous
#include <cuda_runtime.h>

// SparseSphereConv: BS=4, C_IN=C_OUT=32, V=40962, K=9
// out[b,o,v] = mask[b,v] * ( bias[o] + sum_{c,k} (sum_{k'} x[b,c,idx[v,k']] * itp[v,k',k]) * w[o,c,k] )
// mask[b,v] = any_{c,k'} ( x[b,c,idx[v,k']] != 0 )
//
// R4: f32x2-packed math along the k/j axis (4 packed + 1 scalar per 9) and
// VB=4 vertices per barrier cycle (amortize syncs, double gather MLP).

#define V_TOT 40962
#define NBS   4
#define NCI   32
#define NCO   32
#define KNB   9
#define NROWS 128   // NBS * NCI
#define VB    4     // vertices per CTA iteration

typedef unsigned long long ull;

// Scratch: x transposed to [V][128], row r = b*32 + c  (21 MB, L2-resident)
static __device__ float g_xt[(size_t)V_TOT * NROWS];

// ---------------- packed fp32 helpers (sm_103a f32x2 pipe) ----------------
__device__ __forceinline__ ull ffma2(ull a, ull b, ull c) {
    ull d; asm("fma.rn.f32x2 %0, %1, %2, %3;" : "=l"(d) : "l"(a), "l"(b), "l"(c)); return d;
}
__device__ __forceinline__ ull fadd2(ull a, ull b) {
    ull d; asm("add.rn.f32x2 %0, %1, %2;" : "=l"(d) : "l"(a), "l"(b)); return d;
}
__device__ __forceinline__ ull pack2(float lo, float hi) {
    ull d; asm("mov.b64 %0, {%1, %2};" : "=l"(d) : "f"(lo), "f"(hi)); return d;
}
__device__ __forceinline__ float2 unpack2(ull v) {
    float2 r; asm("mov.b64 {%0, %1}, %2;" : "=f"(r.x), "=f"(r.y) : "l"(v)); return r;
}

// ---------------------------------------------------------------------------
// Kernel 1: transpose x [128 rows (b*32+c), V] -> xt [V][128]
// ---------------------------------------------------------------------------
__global__ void transpose_kernel(const float* __restrict__ x) {
    __shared__ float sh[32][33];
    const int n0 = blockIdx.x * 32;
    const int r0 = blockIdx.y * 32;
    const int tx = threadIdx.x, ty = threadIdx.y;
#pragma unroll
    for (int i = 0; i < 4; i++) {
        const int n = n0 + tx;
        const int r = r0 + ty + 8 * i;
        sh[ty + 8 * i][tx] = (n < V_TOT) ? x[(size_t)r * V_TOT + n] : 0.0f;
    }
    __syncthreads();
#pragma unroll
    for (int i = 0; i < 4; i++) {
        const int n = n0 + ty + 8 * i;
        if (n < V_TOT) g_xt[(size_t)n * NROWS + r0 + tx] = sh[tx][ty + 8 * i];
    }
}

// ---------------------------------------------------------------------------
// Kernel 2: fused gather + interp + conv + mask. 256 threads, VB=4 verts/iter.
// ---------------------------------------------------------------------------
__global__ __launch_bounds__(256, 2)
void sphere_kernel(const int*   __restrict__ nbr,
                   const float* __restrict__ itp,
                   const float* __restrict__ conv_w,
                   const float* __restrict__ conv_b,
                   float*       __restrict__ out)
{
    __shared__ int                 s_idx[VB][KNB];
    __shared__ __align__(16) float s_itp[VB][KNB][12];      // j-rows in [0..8], pad unread
    __shared__ __align__(16) float s_f[VB][NBS][NCI][12];   // interp results
    __shared__ float               s_red[8][VB][NBS][NCO];  // per-cgroup conv partials
    __shared__ int                 s_nz[VB][NBS];

    const int t    = threadIdx.x;
    const int lane = t & 31;
    const int wid  = t >> 5;

    // --- conv-stage identity: warp = c-group, lane = output channel ---
    const int o  = lane;
    const int cg = wid;

    // W slice in registers, k-pair packed: Wk2[ci][kp] = (w[2kp], w[2kp+1]), Wk8 = w[8]
    ull   Wk2[4][4];
    float Wk8[4];
#pragma unroll
    for (int ci = 0; ci < 4; ci++) {
        float wt[KNB];
#pragma unroll
        for (int k = 0; k < KNB; k++)
            wt[k] = conv_w[((size_t)o * NCI + (cg * 4 + ci)) * KNB + k];
#pragma unroll
        for (int kp = 0; kp < 4; kp++) Wk2[ci][kp] = pack2(wt[2 * kp], wt[2 * kp + 1]);
        Wk8[ci] = wt[8];
    }
    const float bias = conv_b[lane];

    // --- interp-stage identity ---
    const int grp = t >> 7;      // vertex-pair group: handles local vertices 2g, 2g+1
    const int rr  = t & 127;     // row = b*32 + c
    const int bI  = rr >> 5;

    const int NGRP = (V_TOT + VB - 1) / VB;  // 10241 (last group: 2 valid vertices)

    for (int p = blockIdx.x; p < NGRP; p += gridDim.x) {
        const int v0 = p * VB;

        // ---- stage 0: per-vertex metadata (guarded for the tail group) ----
        if (t < VB * KNB) {
            const int vl = t / KNB, k = t - KNB * vl;
            const int vg = v0 + vl;
            s_idx[vl][k] = (vg < V_TOT) ? nbr[(size_t)vg * KNB + k] : 0;
        }
#pragma unroll
        for (int e = t; e < VB * KNB * KNB; e += 256) {
            const int vl  = e / (KNB * KNB);
            const int rem = e - vl * (KNB * KNB);
            const int k   = rem / KNB;
            const int j   = rem - KNB * k;
            const int vg  = v0 + vl;
            s_itp[vl][k][j] = (vg < V_TOT) ? itp[(size_t)vg * (KNB * KNB) + rem] : 0.0f;
        }
        __syncthreads();  // A

        // ---- stage 1: gather (coalesced, L2) + mask + packed interp ----
        const int va = grp * 2, vb = grp * 2 + 1;
        float ga[KNB], gb[KNB];
        const float* xb = g_xt + rr;
#pragma unroll
        for (int k = 0; k < KNB; k++) ga[k] = __ldg(xb + (size_t)s_idx[va][k] * NROWS);
#pragma unroll
        for (int k = 0; k < KNB; k++) gb[k] = __ldg(xb + (size_t)s_idx[vb][k] * NROWS);

        bool nza = false, nzb = false;
#pragma unroll
        for (int k = 0; k < KNB; k++) { nza |= (ga[k] != 0.0f); nzb |= (gb[k] != 0.0f); }
        const unsigned ba = __ballot_sync(0xFFFFFFFFu, nza);
        const unsigned bb = __ballot_sync(0xFFFFFFFFu, nzb);
        if (lane == 0) { s_nz[va][bI] = ba ? 1 : 0; s_nz[vb][bI] = bb ? 1 : 0; }

#pragma unroll
        for (int h = 0; h < 2; h++) {
            const int    vloc = (h == 0) ? va : vb;
            const float* g    = (h == 0) ? ga : gb;
            ull f01 = 0, f23 = 0, f45 = 0, f67 = 0; float f8 = 0.0f;
#pragma unroll
            for (int k = 0; k < KNB; k++) {
                const float gk = g[k];
                const ull   g2 = pack2(gk, gk);
                const ulonglong2 ia = *(const ulonglong2*)&s_itp[vloc][k][0];
                const ulonglong2 ib = *(const ulonglong2*)&s_itp[vloc][k][4];
                const float      i8 = s_itp[vloc][k][8];
                f01 = ffma2(g2, ia.x, f01);
                f23 = ffma2(g2, ia.y, f23);
                f45 = ffma2(g2, ib.x, f45);
                f67 = ffma2(g2, ib.y, f67);
                f8  = fmaf(gk, i8, f8);
            }
            float* fr = &s_f[vloc][bI][rr & 31][0];
            ulonglong2 w1; w1.x = f01; w1.y = f23; *(ulonglong2*)fr       = w1;
            ulonglong2 w2; w2.x = f45; w2.y = f67; *(ulonglong2*)(fr + 4) = w2;
            fr[8] = f8;
        }
        __syncthreads();  // B

        // ---- stage 2: conv, k-pair packed FMA, W in registers ----
#pragma unroll
        for (int v = 0; v < VB; v++) {
#pragma unroll
            for (int b = 0; b < NBS; b++) {
                ull a0 = 0, a1 = 0, a2 = 0, a3 = 0; float a8 = 0.0f;
#pragma unroll
                for (int ci = 0; ci < 4; ci++) {
                    const float* fr = &s_f[v][b][cg * 4 + ci][0];
                    const ulonglong2 fa = *(const ulonglong2*)fr;
                    const ulonglong2 fb = *(const ulonglong2*)(fr + 4);
                    const float      f8 = fr[8];
                    a0 = ffma2(fa.x, Wk2[ci][0], a0);
                    a1 = ffma2(fa.y, Wk2[ci][1], a1);
                    a2 = ffma2(fb.x, Wk2[ci][2], a2);
                    a3 = ffma2(fb.y, Wk2[ci][3], a3);
                    a8 = fmaf(f8, Wk8[ci], a8);
                }
                const ull    sp = fadd2(fadd2(a0, a1), fadd2(a2, a3));
                const float2 sf = unpack2(sp);
                s_red[cg][v][b][o] = sf.x + sf.y + a8;
            }
        }
        __syncthreads();  // C

        // ---- stage 3: reduce 8 c-groups, bias, mask, store ----
#pragma unroll
        for (int r = 0; r < 2; r++) {
            const int e  = t + r * 256;
            const int v  = e >> 7;
            const int b  = (e >> 5) & 3;
            const int oo = e & 31;   // == lane, so `bias` matches
            float s = 0.0f;
#pragma unroll
            for (int w8 = 0; w8 < 8; w8++) s += s_red[w8][v][b][oo];
            s = (s + bias) * (float)s_nz[v][b];
            const int vg = v0 + v;
            if (vg < V_TOT)
                out[((size_t)b * NCO + oo) * V_TOT + vg] = s;
        }
        // No trailing barrier: next iter's stage-0 writes (s_idx/s_itp) are
        // ordered after sync C and all cross-iter readers finished before B/C.
    }
}

extern "C" void kernel_launch(void* const* d_in, const int* in_sizes, int n_in,
                              void* d_out, int out_size) {
    (void)in_sizes; (void)n_in; (void)out_size;
    const float* x      = (const float*)d_in[0];
    const int*   nbr    = (const int*)  d_in[1];
    const float* itp    = (const float*)d_in[2];
    const float* conv_w = (const float*)d_in[3];
    const float* conv_b = (const float*)d_in[4];
    float*       out    = (float*)d_out;

    dim3 tb(32, 8);
    dim3 tg((V_TOT + 31) / 32, NROWS / 32);
    transpose_kernel<<<tg, tb>>>(x);

    sphere_kernel<<<608, 256>>>(nbr, itp, conv_w, conv_b, out);
}

// round 8
// speedup vs baseline: 1.2370x; 1.1003x over previous
#include <cuda_runtime.h>

// SparseSphereConv: BS=4, C_IN=C_OUT=32, V=40962, K=9
// out[b,o,v] = mask[b,v] * ( bias[o] + sum_{c,k} (sum_{k'} x[b,c,idx[v,k']] * itp[v,k',k]) * w[o,c,k] )
// mask[b,v] = any_{c,k'} ( x[b,c,idx[v,k']] != 0 )
//
// R7: L1-wavefront diet. f8-segregated s_f (144 vs 192 stage-2 LDS/thread),
// contiguous STS.128 s_f writes, coalesced 16B-sector global stores,
// metadata double-buffer + prefetch (2 barriers/group), conflict-free s_red.

#define V_TOT 40962
#define NBS   4
#define NCI   32
#define NCO   32
#define KNB   9
#define NROWS 128   // NBS * NCI
#define VB    4     // vertices per group
#define NGRP  10241 // ceil(V_TOT / VB)
#define SRED_P 34   // s_red inner pad: 4*34 mod 32 = 8 -> conflict-free r/w

typedef unsigned long long ull;

// x transposed to [V][128], row r = b*32 + c  (21 MB, L2-resident)
static __device__ float g_xt[(size_t)V_TOT * NROWS];

// ---------------- packed fp32 helpers (sm_103a f32x2 pipe) ----------------
__device__ __forceinline__ ull ffma2(ull a, ull b, ull c) {
    ull d; asm("fma.rn.f32x2 %0, %1, %2, %3;" : "=l"(d) : "l"(a), "l"(b), "l"(c)); return d;
}
__device__ __forceinline__ ull fadd2(ull a, ull b) {
    ull d; asm("add.rn.f32x2 %0, %1, %2;" : "=l"(d) : "l"(a), "l"(b)); return d;
}
__device__ __forceinline__ ull pack2(float lo, float hi) {
    ull d; asm("mov.b64 %0, {%1, %2};" : "=l"(d) : "f"(lo), "f"(hi)); return d;
}
__device__ __forceinline__ float2 unpack2(ull v) {
    float2 r; asm("mov.b64 {%0, %1}, %2;" : "=f"(r.x), "=f"(r.y) : "l"(v)); return r;
}

// ---------------------------------------------------------------------------
// Kernel 1: transpose x [128 rows (b*32+c), V] -> xt [V][128]
// ---------------------------------------------------------------------------
__global__ void transpose_kernel(const float* __restrict__ x) {
    __shared__ float sh[32][33];
    const int n0 = blockIdx.x * 32;
    const int r0 = blockIdx.y * 32;
    const int tx = threadIdx.x, ty = threadIdx.y;
#pragma unroll
    for (int i = 0; i < 4; i++) {
        const int n = n0 + tx;
        const int r = r0 + ty + 8 * i;
        sh[ty + 8 * i][tx] = (n < V_TOT) ? x[(size_t)r * V_TOT + n] : 0.0f;
    }
    __syncthreads();
#pragma unroll
    for (int i = 0; i < 4; i++) {
        const int n = n0 + ty + 8 * i;
        if (n < V_TOT) g_xt[(size_t)n * NROWS + r0 + tx] = sh[tx][ty + 8 * i];
    }
}

// ---------------------------------------------------------------------------
// Kernel 2: fused gather + interp + conv + mask.
// ---------------------------------------------------------------------------
__global__ __launch_bounds__(256, 2)
void sphere_kernel(const int*   __restrict__ nbr,
                   const float* __restrict__ itp,
                   const float* __restrict__ conv_w,
                   const float* __restrict__ conv_b,
                   float*       __restrict__ out)
{
    __shared__ __align__(16) float4 s_fA[VB][NBS][NCI];     // interp k0..3
    __shared__ __align__(16) float4 s_fB[VB][NBS][NCI];     // interp k4..7
    __shared__ __align__(16) float  s_f8[VB][NBS][NCI];     // interp k8
    __shared__ float                s_red[8][VB][NBS][SRED_P]; // cgroup partials [cg][v][b][o]
    __shared__ __align__(16) float  s_itp[2][VB][KNB][12];  // double-buffered metadata
    __shared__ int                  s_idx[2][VB][KNB];
    __shared__ int                  s_nz[2][VB][NBS];

    const int t    = threadIdx.x;
    const int lane = t & 31;
    const int wid  = t >> 5;

    // --- conv identity: warp = c-group, lane = output channel ---
    const int o  = lane;
    const int cg = wid;

    // W in registers, k-pair packed. W8p packs w[k=8] for c-pairs.
    ull Wk2[4][4];
    ull W8p[2];
    {
        float w8[4];
#pragma unroll
        for (int ci = 0; ci < 4; ci++) {
            float wt[KNB];
#pragma unroll
            for (int k = 0; k < KNB; k++)
                wt[k] = conv_w[((size_t)o * NCI + (cg * 4 + ci)) * KNB + k];
#pragma unroll
            for (int kp = 0; kp < 4; kp++) Wk2[ci][kp] = pack2(wt[2 * kp], wt[2 * kp + 1]);
            w8[ci] = wt[8];
        }
        W8p[0] = pack2(w8[0], w8[1]);
        W8p[1] = pack2(w8[2], w8[3]);
    }

    // --- stage-3 identity: e = t (+256): b=e>>7, oo=(e>>2)&31, vloc=e&3 ---
    const int oo3 = (t >> 2) & 31;   // same for both halves
    const int vl3 = t & 3;
    const int b3  = t >> 7;          // second half uses b3+2
    const float bias3 = conv_b[oo3];

    // --- interp identity ---
    const int grp = t >> 7;          // local vertex pair base 2*grp
    const int rr  = t & 127;
    const int bI  = rr >> 5;
    const int cI  = rr & 31;

    const int g0 = blockIdx.x;
    int p = 0;

    // ---- prime: metadata for first group into buffer 0 ----
    if (g0 < NGRP) {
        const int v0p = g0 * VB;
        if (t < VB * KNB) {
            const int vl = t / KNB, k = t - KNB * vl;
            const int vg = v0p + vl;
            s_idx[0][vl][k] = (vg < V_TOT) ? nbr[(size_t)vg * KNB + k] : 0;
        }
#pragma unroll
        for (int e = t; e < VB * KNB * KNB; e += 256) {
            const int vl  = e / 81;
            const int rem = e - 81 * vl;
            const int vg  = v0p + vl;
            s_itp[0][vl][rem / KNB][rem % KNB] =
                (vg < V_TOT) ? itp[(size_t)vg * 81 + rem] : 0.0f;
        }
    }
    __syncthreads();

    for (int g = g0; g < NGRP; g += gridDim.x) {
        const int v0 = g * VB;

        // ---- stage 1: gather + mask + interp (meta buf p) ----
        const int va = grp * 2, vb = grp * 2 + 1;
        float ga[KNB], gb[KNB];
        const float* xb = g_xt + rr;
#pragma unroll
        for (int k = 0; k < KNB; k++) ga[k] = __ldg(xb + (size_t)s_idx[p][va][k] * NROWS);
#pragma unroll
        for (int k = 0; k < KNB; k++) gb[k] = __ldg(xb + (size_t)s_idx[p][vb][k] * NROWS);

        bool nza = false, nzb = false;
#pragma unroll
        for (int k = 0; k < KNB; k++) { nza |= (ga[k] != 0.0f); nzb |= (gb[k] != 0.0f); }
        const unsigned ba = __ballot_sync(0xFFFFFFFFu, nza);
        const unsigned bb = __ballot_sync(0xFFFFFFFFu, nzb);
        if (lane == 0) { s_nz[p][va][bI] = ba ? 1 : 0; s_nz[p][vb][bI] = bb ? 1 : 0; }

#pragma unroll
        for (int h = 0; h < 2; h++) {
            const int    vloc = (h == 0) ? va : vb;
            const float* g_   = (h == 0) ? ga : gb;
            ull f01 = 0, f23 = 0, f45 = 0, f67 = 0; float f8 = 0.0f;
#pragma unroll
            for (int k = 0; k < KNB; k++) {
                const float gk = g_[k];
                const ull   g2 = pack2(gk, gk);
                const ulonglong2 ia = *(const ulonglong2*)&s_itp[p][vloc][k][0];
                const ulonglong2 ib = *(const ulonglong2*)&s_itp[p][vloc][k][4];
                const float      i8 = s_itp[p][vloc][k][8];
                f01 = ffma2(g2, ia.x, f01);
                f23 = ffma2(g2, ia.y, f23);
                f45 = ffma2(g2, ib.x, f45);
                f67 = ffma2(g2, ib.y, f67);
                f8  = fmaf(gk, i8, f8);
            }
            ulonglong2 wA; wA.x = f01; wA.y = f23;
            ulonglong2 wB; wB.x = f45; wB.y = f67;
            *(ulonglong2*)&s_fA[vloc][bI][cI] = wA;   // contiguous STS.128 over cI
            *(ulonglong2*)&s_fB[vloc][bI][cI] = wB;
            s_f8[vloc][bI][cI] = f8;
        }

        // ---- prefetch metadata for next group into buf p^1 ----
        const int gn = g + gridDim.x;
        if (gn < NGRP) {
            const int pn  = p ^ 1;
            const int v0n = gn * VB;
            if (t < VB * KNB) {
                const int vl = t / KNB, k = t - KNB * vl;
                const int vg = v0n + vl;
                s_idx[pn][vl][k] = (vg < V_TOT) ? nbr[(size_t)vg * KNB + k] : 0;
            }
#pragma unroll
            for (int e = t; e < VB * KNB * KNB; e += 256) {
                const int vl  = e / 81;
                const int rem = e - 81 * vl;
                const int vg  = v0n + vl;
                s_itp[pn][vl][rem / KNB][rem % KNB] =
                    (vg < V_TOT) ? itp[(size_t)vg * 81 + rem] : 0.0f;
            }
        }
        __syncthreads();  // B: s_f ready; also orders prev stage-3 s_red reads

        // ---- stage 2: conv, k-pair packed FMA, W in registers ----
#pragma unroll
        for (int v = 0; v < VB; v++) {
#pragma unroll
            for (int b = 0; b < NBS; b++) {
                const ulonglong2* pA = (const ulonglong2*)&s_fA[v][b][cg * 4];
                const ulonglong2* pB = (const ulonglong2*)&s_fB[v][b][cg * 4];
                ull a0 = 0, a1 = 0, a2 = 0, a3 = 0, a8 = 0;
#pragma unroll
                for (int ci = 0; ci < 4; ci++) {
                    const ulonglong2 fa = pA[ci];
                    const ulonglong2 fb = pB[ci];
                    a0 = ffma2(fa.x, Wk2[ci][0], a0);
                    a1 = ffma2(fa.y, Wk2[ci][1], a1);
                    a2 = ffma2(fb.x, Wk2[ci][2], a2);
                    a3 = ffma2(fb.y, Wk2[ci][3], a3);
                }
                const ulonglong2 f8p = *(const ulonglong2*)&s_f8[v][b][cg * 4];
                a8 = ffma2(f8p.x, W8p[0], a8);
                a8 = ffma2(f8p.y, W8p[1], a8);

                ull sp = fadd2(fadd2(a0, a1), fadd2(a2, a3));
                sp = fadd2(sp, a8);
                const float2 sf = unpack2(sp);
                s_red[cg][v][b][o] = sf.x + sf.y;   // stride-1 over lanes: conflict-free
            }
        }
        __syncthreads();  // C: s_red ready

        // ---- stage 3: reduce 8 cgroups, bias, mask, coalesced store ----
#pragma unroll
        for (int r = 0; r < 2; r++) {
            const int b = b3 + r * 2;
            float s = 0.0f;
#pragma unroll
            for (int w8 = 0; w8 < 8; w8++)
                s += s_red[w8][vl3][b][oo3];        // banks 8*vl3+oo_low: conflict-free
            s = (s + bias3) * (float)s_nz[p][vl3][b];
            const int vg = v0 + vl3;
            if (vg < V_TOT)
                out[((size_t)b * NCO + oo3) * V_TOT + vg] = s;  // 4 consecutive v per 4 lanes
        }

        p ^= 1;
    }
}

extern "C" void kernel_launch(void* const* d_in, const int* in_sizes, int n_in,
                              void* d_out, int out_size) {
    (void)in_sizes; (void)n_in; (void)out_size;
    const float* x      = (const float*)d_in[0];
    const int*   nbr    = (const int*)  d_in[1];
    const float* itp    = (const float*)d_in[2];
    const float* conv_w = (const float*)d_in[3];
    const float* conv_b = (const float*)d_in[4];
    float*       out    = (float*)d_out;

    dim3 tb(32, 8);
    dim3 tg((V_TOT + 31) / 32, NROWS / 32);
    transpose_kernel<<<tg, tb>>>(x);

    // 296 = 2 CTAs x 148 SMs: fully-resident persistent grid
    sphere_kernel<<<296, 256>>>(nbr, itp, conv_w, conv_b, out);
}

// round 12
// speedup vs baseline: 1.3119x; 1.0606x over previous
#include <cuda_runtime.h>

// SparseSphereConv: BS=4, C_IN=C_OUT=32, V=40962, K=9
// out[b,o,v] = mask[b,v] * ( bias[o] + sum_{c,k} (sum_{k'} x[b,c,idx[v,k']] * itp[v,k',k]) * w[o,c,k] )
// mask[b,v] = any_{c,k'} ( x[b,c,idx[v,k']] != 0 )
//
// R8: stage-1 remap thread = (1 vertex, 2 adjacent-c rows): itp broadcasts
// halved (432->216/group), gather insts halved via LDG.64, f8 stores fused.
// Stage 2/3 and double-buffered metadata pipeline unchanged from R7.

#define V_TOT 40962
#define NBS   4
#define NCI   32
#define NCO   32
#define KNB   9
#define NROWS 128   // NBS * NCI
#define VB    4     // vertices per group
#define NGRP  10241 // ceil(V_TOT / VB)
#define SRED_P 34   // s_red inner pad: conflict-free r/w

typedef unsigned long long ull;

// x transposed to [V][128], row r = b*32 + c  (21 MB, L2-resident)
static __device__ float g_xt[(size_t)V_TOT * NROWS];

// ---------------- packed fp32 helpers (sm_103a f32x2 pipe) ----------------
__device__ __forceinline__ ull ffma2(ull a, ull b, ull c) {
    ull d; asm("fma.rn.f32x2 %0, %1, %2, %3;" : "=l"(d) : "l"(a), "l"(b), "l"(c)); return d;
}
__device__ __forceinline__ ull fadd2(ull a, ull b) {
    ull d; asm("add.rn.f32x2 %0, %1, %2;" : "=l"(d) : "l"(a), "l"(b)); return d;
}
__device__ __forceinline__ ull pack2(float lo, float hi) {
    ull d; asm("mov.b64 %0, {%1, %2};" : "=l"(d) : "f"(lo), "f"(hi)); return d;
}
__device__ __forceinline__ float2 unpack2(ull v) {
    float2 r; asm("mov.b64 {%0, %1}, %2;" : "=f"(r.x), "=f"(r.y) : "l"(v)); return r;
}

// ---------------------------------------------------------------------------
// Kernel 1: transpose x [128 rows (b*32+c), V] -> xt [V][128]
// ---------------------------------------------------------------------------
__global__ void transpose_kernel(const float* __restrict__ x) {
    __shared__ float sh[32][33];
    const int n0 = blockIdx.x * 32;
    const int r0 = blockIdx.y * 32;
    const int tx = threadIdx.x, ty = threadIdx.y;
#pragma unroll
    for (int i = 0; i < 4; i++) {
        const int n = n0 + tx;
        const int r = r0 + ty + 8 * i;
        sh[ty + 8 * i][tx] = (n < V_TOT) ? x[(size_t)r * V_TOT + n] : 0.0f;
    }
    __syncthreads();
#pragma unroll
    for (int i = 0; i < 4; i++) {
        const int n = n0 + ty + 8 * i;
        if (n < V_TOT) g_xt[(size_t)n * NROWS + r0 + tx] = sh[tx][ty + 8 * i];
    }
}

// ---------------------------------------------------------------------------
// Kernel 2: fused gather + interp + conv + mask.
// ---------------------------------------------------------------------------
__global__ __launch_bounds__(256, 2)
void sphere_kernel(const int*   __restrict__ nbr,
                   const float* __restrict__ itp,
                   const float* __restrict__ conv_w,
                   const float* __restrict__ conv_b,
                   float*       __restrict__ out)
{
    __shared__ __align__(16) float4 s_fA[VB][NBS][NCI];     // interp k0..3
    __shared__ __align__(16) float4 s_fB[VB][NBS][NCI];     // interp k4..7
    __shared__ __align__(16) float  s_f8[VB][NBS][NCI];     // interp k8
    __shared__ float                s_red[8][VB][NBS][SRED_P]; // [cg][v][b][o]
    __shared__ __align__(16) float  s_itp[2][VB][KNB][12];  // double-buffered metadata
    __shared__ int                  s_idx[2][VB][KNB];
    __shared__ int                  s_nz[2][VB][NBS];

    const int t    = threadIdx.x;
    const int lane = t & 31;
    const int wid  = t >> 5;

    // --- conv identity: warp = c-group, lane = output channel ---
    const int o  = lane;
    const int cg = wid;

    // W in registers, k-pair packed. W8p packs w[k=8] for c-pairs.
    ull Wk2[4][4];
    ull W8p[2];
    {
        float w8[4];
#pragma unroll
        for (int ci = 0; ci < 4; ci++) {
            float wt[KNB];
#pragma unroll
            for (int k = 0; k < KNB; k++)
                wt[k] = conv_w[((size_t)o * NCI + (cg * 4 + ci)) * KNB + k];
#pragma unroll
            for (int kp = 0; kp < 4; kp++) Wk2[ci][kp] = pack2(wt[2 * kp], wt[2 * kp + 1]);
            w8[ci] = wt[8];
        }
        W8p[0] = pack2(w8[0], w8[1]);
        W8p[1] = pack2(w8[2], w8[3]);
    }

    // --- stage-3 identity: e = t (+256): b=e>>7, oo=(e>>2)&31, vloc=e&3 ---
    const int oo3 = (t >> 2) & 31;
    const int vl3 = t & 3;
    const int b3  = t >> 7;
    const float bias3 = conv_b[oo3];

    // --- stage-1 identity: warp -> (vertex, b-pair half); lane -> (b, c-pair) ---
    const int vI   = wid >> 1;                 // vertex 0..3
    const int half = wid & 1;                  // b-pair: {0,1} or {2,3}
    const int bW   = 2 * half + (lane >> 4);   // this thread's b
    const int c0   = 2 * (lane & 15);          // rows (bW,c0) and (bW,c0+1)
    const int rowbase = bW * 32 + c0;          // even -> 8B-aligned gather

    const int g0 = blockIdx.x;
    int p = 0;

    // ---- prime: metadata for first group into buffer 0 ----
    if (g0 < NGRP) {
        const int v0p = g0 * VB;
        if (t < VB * KNB) {
            const int vl = t / KNB, k = t - KNB * vl;
            const int vg = v0p + vl;
            s_idx[0][vl][k] = (vg < V_TOT) ? nbr[(size_t)vg * KNB + k] : 0;
        }
#pragma unroll
        for (int e = t; e < VB * KNB * KNB; e += 256) {
            const int vl  = e / 81;
            const int rem = e - 81 * vl;
            const int vg  = v0p + vl;
            s_itp[0][vl][rem / KNB][rem % KNB] =
                (vg < V_TOT) ? itp[(size_t)vg * 81 + rem] : 0.0f;
        }
    }
    __syncthreads();

    for (int g = g0; g < NGRP; g += gridDim.x) {
        const int v0 = g * VB;

        // ---- stage 1: gather (LDG.64: 2 c-rows/load) + mask + interp ----
        float2 gv[KNB];
        const float2* xb = (const float2*)(g_xt + rowbase);
#pragma unroll
        for (int k = 0; k < KNB; k++)
            gv[k] = __ldg(xb + (size_t)s_idx[p][vI][k] * (NROWS / 2));

        bool nz = false;
#pragma unroll
        for (int k = 0; k < KNB; k++) nz |= (gv[k].x != 0.0f) | (gv[k].y != 0.0f);
        const unsigned bm = __ballot_sync(0xFFFFFFFFu, nz);
        if (lane == 0) {
            s_nz[p][vI][2 * half]     = (bm & 0xFFFFu) ? 1 : 0;
            s_nz[p][vI][2 * half + 1] = (bm >> 16)     ? 1 : 0;
        }

        // interp for both rows; itp registers shared across the row pair
        {
            ull xA01 = 0, xA23 = 0, xA45 = 0, xA67 = 0; float xA8 = 0.0f;
            ull yA01 = 0, yA23 = 0, yA45 = 0, yA67 = 0; float yA8 = 0.0f;
#pragma unroll
            for (int k = 0; k < KNB; k++) {
                const ulonglong2 ia = *(const ulonglong2*)&s_itp[p][vI][k][0];
                const ulonglong2 ib = *(const ulonglong2*)&s_itp[p][vI][k][4];
                const float      i8 = s_itp[p][vI][k][8];
                const float gx = gv[k].x, gy = gv[k].y;
                const ull g2x = pack2(gx, gx);
                const ull g2y = pack2(gy, gy);
                xA01 = ffma2(g2x, ia.x, xA01);
                xA23 = ffma2(g2x, ia.y, xA23);
                xA45 = ffma2(g2x, ib.x, xA45);
                xA67 = ffma2(g2x, ib.y, xA67);
                xA8  = fmaf(gx, i8, xA8);
                yA01 = ffma2(g2y, ia.x, yA01);
                yA23 = ffma2(g2y, ia.y, yA23);
                yA45 = ffma2(g2y, ib.x, yA45);
                yA67 = ffma2(g2y, ib.y, yA67);
                yA8  = fmaf(gy, i8, yA8);
            }
            ulonglong2 w;
            w.x = xA01; w.y = xA23; *(ulonglong2*)&s_fA[vI][bW][c0]     = w;
            w.x = yA01; w.y = yA23; *(ulonglong2*)&s_fA[vI][bW][c0 + 1] = w;
            w.x = xA45; w.y = xA67; *(ulonglong2*)&s_fB[vI][bW][c0]     = w;
            w.x = yA45; w.y = yA67; *(ulonglong2*)&s_fB[vI][bW][c0 + 1] = w;
            *(float2*)&s_f8[vI][bW][c0] = make_float2(xA8, yA8);
        }

        // ---- prefetch metadata for next group into buf p^1 ----
        const int gn = g + gridDim.x;
        if (gn < NGRP) {
            const int pn  = p ^ 1;
            const int v0n = gn * VB;
            if (t < VB * KNB) {
                const int vl = t / KNB, k = t - KNB * vl;
                const int vg = v0n + vl;
                s_idx[pn][vl][k] = (vg < V_TOT) ? nbr[(size_t)vg * KNB + k] : 0;
            }
#pragma unroll
            for (int e = t; e < VB * KNB * KNB; e += 256) {
                const int vl  = e / 81;
                const int rem = e - 81 * vl;
                const int vg  = v0n + vl;
                s_itp[pn][vl][rem / KNB][rem % KNB] =
                    (vg < V_TOT) ? itp[(size_t)vg * 81 + rem] : 0.0f;
            }
        }
        __syncthreads();  // B: s_f ready; also orders prev stage-3 s_red reads

        // ---- stage 2: conv, k-pair packed FMA, W in registers ----
#pragma unroll
        for (int v = 0; v < VB; v++) {
#pragma unroll
            for (int b = 0; b < NBS; b++) {
                const ulonglong2* pA = (const ulonglong2*)&s_fA[v][b][cg * 4];
                const ulonglong2* pB = (const ulonglong2*)&s_fB[v][b][cg * 4];
                ull a0 = 0, a1 = 0, a2 = 0, a3 = 0, a8 = 0;
#pragma unroll
                for (int ci = 0; ci < 4; ci++) {
                    const ulonglong2 fa = pA[ci];
                    const ulonglong2 fb = pB[ci];
                    a0 = ffma2(fa.x, Wk2[ci][0], a0);
                    a1 = ffma2(fa.y, Wk2[ci][1], a1);
                    a2 = ffma2(fb.x, Wk2[ci][2], a2);
                    a3 = ffma2(fb.y, Wk2[ci][3], a3);
                }
                const ulonglong2 f8p = *(const ulonglong2*)&s_f8[v][b][cg * 4];
                a8 = ffma2(f8p.x, W8p[0], a8);
                a8 = ffma2(f8p.y, W8p[1], a8);

                ull sp = fadd2(fadd2(a0, a1), fadd2(a2, a3));
                sp = fadd2(sp, a8);
                const float2 sf = unpack2(sp);
                s_red[cg][v][b][o] = sf.x + sf.y;
            }
        }
        __syncthreads();  // C: s_red ready

        // ---- stage 3: reduce 8 cgroups, bias, mask, coalesced store ----
#pragma unroll
        for (int r = 0; r < 2; r++) {
            const int b = b3 + r * 2;
            float s = 0.0f;
#pragma unroll
            for (int w8 = 0; w8 < 8; w8++)
                s += s_red[w8][vl3][b][oo3];
            s = (s + bias3) * (float)s_nz[p][vl3][b];
            const int vg = v0 + vl3;
            if (vg < V_TOT)
                out[((size_t)b * NCO + oo3) * V_TOT + vg] = s;
        }

        p ^= 1;
    }
}

extern "C" void kernel_launch(void* const* d_in, const int* in_sizes, int n_in,
                              void* d_out, int out_size) {
    (void)in_sizes; (void)n_in; (void)out_size;
    const float* x      = (const float*)d_in[0];
    const int*   nbr    = (const int*)  d_in[1];
    const float* itp    = (const float*)d_in[2];
    const float* conv_w = (const float*)d_in[3];
    const float* conv_b = (const float*)d_in[4];
    float*       out    = (float*)d_out;

    dim3 tb(32, 8);
    dim3 tg((V_TOT + 31) / 32, NROWS / 32);
    transpose_kernel<<<tg, tb>>>(x);

    // 296 = 2 CTAs x 148 SMs: fully-resident persistent grid
    sphere_kernel<<<296, 256>>>(nbr, itp, conv_w, conv_b, out);
}

// round 16
// speedup vs baseline: 1.4011x; 1.0680x over previous
#include <cuda_runtime.h>

// SparseSphereConv: BS=4, C_IN=C_OUT=32, V=40962, K=9
// out[b,o,v] = mask[b,v] * ( bias[o] + sum_{c,k} (sum_{k'} x[b,c,idx[v,k']] * itp[v,k',k]) * w[o,c,k] )
// mask[b,v] = any_{c,k'} ( x[b,c,idx[v,k']] != 0 )
//
// R16 = R15 resubmit (R15 bench was an infra failure; kernel never ran).
// R12 theory under test: weights evicted from permanent registers into
// __device__ arrays (prep kernel <<<16,256>>> covers all 4096 g_w2 entries —
// R14's rel_err=0.85 was an under-launched prep grid), reloaded at stage-2
// entry each group (L1-hit, lane-coalesced). Stage-1/stage-2 register peaks
// disjoint -> __launch_bounds__(256,3) -> 3 CTAs/SM, +50% warps.

#define V_TOT 40962
#define NBS   4
#define NCI   32
#define NCO   32
#define KNB   9
#define NROWS 128   // NBS * NCI
#define VB    4     // vertices per group
#define NGRP  10241 // ceil(V_TOT / VB)
#define SRED_P 34   // s_red inner pad: conflict-free r/w

typedef unsigned long long ull;

// x transposed to [V][128], row r = b*32 + c  (21 MB, L2-resident)
static __device__ float g_xt[(size_t)V_TOT * NROWS];
// packed conv weights: g_w2[((cg*4+kp)*4+ci)*32+o] = (w[o][cg*4+ci][2kp], w[..][2kp+1])
static __device__ ull g_w2[8 * 4 * 4 * 32];
// packed k=8 tail:    g_w8[(cg*2+pr)*32+o] = (w8[ci=2pr], w8[ci=2pr+1])
static __device__ ull g_w8[8 * 2 * 32];

// ---------------- packed fp32 helpers (sm_103a f32x2 pipe) ----------------
__device__ __forceinline__ ull ffma2(ull a, ull b, ull c) {
    ull d; asm("fma.rn.f32x2 %0, %1, %2, %3;" : "=l"(d) : "l"(a), "l"(b), "l"(c)); return d;
}
__device__ __forceinline__ ull fadd2(ull a, ull b) {
    ull d; asm("add.rn.f32x2 %0, %1, %2;" : "=l"(d) : "l"(a), "l"(b)); return d;
}
__device__ __forceinline__ ull pack2(float lo, float hi) {
    ull d; asm("mov.b64 %0, {%1, %2};" : "=l"(d) : "f"(lo), "f"(hi)); return d;
}
__device__ __forceinline__ float2 unpack2(ull v) {
    float2 r; asm("mov.b64 {%0, %1}, %2;" : "=f"(r.x), "=f"(r.y) : "l"(v)); return r;
}

// ---------------------------------------------------------------------------
// Kernel 0: pack conv weights for lane-coalesced stage-2 reloads
// Needs >= 4096 threads: g_w2 has 8*4*4*32 = 4096 entries.
// ---------------------------------------------------------------------------
__global__ void wprep_kernel(const float* __restrict__ conv_w) {
    const int t = blockIdx.x * 256 + threadIdx.x;
    if (t < 8 * 4 * 4 * 32) {
        const int o  = t & 31;
        int r = t >> 5;
        const int ci = r & 3;  r >>= 2;
        const int kp = r & 3;  r >>= 2;
        const int cg = r;
        const float* wt = conv_w + ((size_t)o * NCI + (cg * 4 + ci)) * KNB;
        g_w2[t] = pack2(wt[2 * kp], wt[2 * kp + 1]);
    }
    if (t < 8 * 2 * 32) {
        const int o  = t & 31;
        const int pr = (t >> 5) & 1;
        const int cg = t >> 6;
        const float a = conv_w[((size_t)o * NCI + (cg * 4 + 2 * pr)) * KNB + 8];
        const float b = conv_w[((size_t)o * NCI + (cg * 4 + 2 * pr + 1)) * KNB + 8];
        g_w8[t] = pack2(a, b);
    }
}

// ---------------------------------------------------------------------------
// Kernel 1: transpose x [128 rows (b*32+c), V] -> xt [V][128]
// ---------------------------------------------------------------------------
__global__ void transpose_kernel(const float* __restrict__ x) {
    __shared__ float sh[32][33];
    const int n0 = blockIdx.x * 32;
    const int r0 = blockIdx.y * 32;
    const int tx = threadIdx.x, ty = threadIdx.y;
#pragma unroll
    for (int i = 0; i < 4; i++) {
        const int n = n0 + tx;
        const int r = r0 + ty + 8 * i;
        sh[ty + 8 * i][tx] = (n < V_TOT) ? x[(size_t)r * V_TOT + n] : 0.0f;
    }
    __syncthreads();
#pragma unroll
    for (int i = 0; i < 4; i++) {
        const int n = n0 + ty + 8 * i;
        if (n < V_TOT) g_xt[(size_t)n * NROWS + r0 + tx] = sh[tx][ty + 8 * i];
    }
}

// ---------------------------------------------------------------------------
// Kernel 2: fused gather + interp + conv + mask. 3 CTAs/SM.
// ---------------------------------------------------------------------------
__global__ __launch_bounds__(256, 3)
void sphere_kernel(const int*   __restrict__ nbr,
                   const float* __restrict__ itp,
                   const float* __restrict__ conv_b,
                   float*       __restrict__ out)
{
    __shared__ __align__(16) float4 s_fA[VB][NBS][NCI];     // interp k0..3
    __shared__ __align__(16) float4 s_fB[VB][NBS][NCI];     // interp k4..7
    __shared__ __align__(16) float  s_f8[VB][NBS][NCI];     // interp k8
    __shared__ float                s_red[8][VB][NBS][SRED_P]; // [cg][v][b][o]
    __shared__ __align__(16) float  s_itp[2][VB][KNB][12];  // double-buffered metadata
    __shared__ int                  s_idx[2][VB][KNB];
    __shared__ int                  s_nz[2][VB][NBS];

    const int t    = threadIdx.x;
    const int lane = t & 31;
    const int wid  = t >> 5;

    // --- conv identity: warp = c-group, lane = output channel ---
    const int o  = lane;
    const int cg = wid;
    const ull* wbase2 = g_w2 + (size_t)cg * (4 * 4 * 32) + o;
    const ull* wbase8 = g_w8 + (size_t)cg * (2 * 32) + o;

    // --- stage-3 identity: e = t (+256): b=e>>7, oo=(e>>2)&31, vloc=e&3 ---
    const int oo3 = (t >> 2) & 31;
    const int vl3 = t & 3;
    const int b3  = t >> 7;
    const float bias3 = conv_b[oo3];

    // --- stage-1 identity: warp -> (vertex, b-pair half); lane -> (b, c-pair) ---
    const int vI   = wid >> 1;                 // vertex 0..3
    const int half = wid & 1;                  // b-pair: {0,1} or {2,3}
    const int bW   = 2 * half + (lane >> 4);   // this thread's b
    const int c0   = 2 * (lane & 15);          // rows (bW,c0) and (bW,c0+1)
    const int rowbase = bW * 32 + c0;          // even -> 8B-aligned gather

    const int g0 = blockIdx.x;
    int p = 0;

    // ---- prime: metadata for first group into buffer 0 ----
    if (g0 < NGRP) {
        const int v0p = g0 * VB;
        if (t < VB * KNB) {
            const int vl = t / KNB, k = t - KNB * vl;
            const int vg = v0p + vl;
            s_idx[0][vl][k] = (vg < V_TOT) ? nbr[(size_t)vg * KNB + k] : 0;
        }
#pragma unroll
        for (int e = t; e < VB * KNB * KNB; e += 256) {
            const int vl  = e / 81;
            const int rem = e - 81 * vl;
            const int vg  = v0p + vl;
            s_itp[0][vl][rem / KNB][rem % KNB] =
                (vg < V_TOT) ? itp[(size_t)vg * 81 + rem] : 0.0f;
        }
    }
    __syncthreads();

    for (int g = g0; g < NGRP; g += gridDim.x) {
        const int v0 = g * VB;

        // ---- stage 1: gather (LDG.64: 2 c-rows/load) + mask + interp ----
        float2 gv[KNB];
        const float2* xb = (const float2*)(g_xt + rowbase);
#pragma unroll
        for (int k = 0; k < KNB; k++)
            gv[k] = __ldg(xb + (size_t)s_idx[p][vI][k] * (NROWS / 2));

        bool nz = false;
#pragma unroll
        for (int k = 0; k < KNB; k++) nz |= (gv[k].x != 0.0f) | (gv[k].y != 0.0f);
        const unsigned bm = __ballot_sync(0xFFFFFFFFu, nz);
        if (lane == 0) {
            s_nz[p][vI][2 * half]     = (bm & 0xFFFFu) ? 1 : 0;
            s_nz[p][vI][2 * half + 1] = (bm >> 16)     ? 1 : 0;
        }

        // interp for both rows; itp registers shared across the row pair
        {
            ull xA01 = 0, xA23 = 0, xA45 = 0, xA67 = 0; float xA8 = 0.0f;
            ull yA01 = 0, yA23 = 0, yA45 = 0, yA67 = 0; float yA8 = 0.0f;
#pragma unroll
            for (int k = 0; k < KNB; k++) {
                const ulonglong2 ia = *(const ulonglong2*)&s_itp[p][vI][k][0];
                const ulonglong2 ib = *(const ulonglong2*)&s_itp[p][vI][k][4];
                const float      i8 = s_itp[p][vI][k][8];
                const float gx = gv[k].x, gy = gv[k].y;
                const ull g2x = pack2(gx, gx);
                const ull g2y = pack2(gy, gy);
                xA01 = ffma2(g2x, ia.x, xA01);
                xA23 = ffma2(g2x, ia.y, xA23);
                xA45 = ffma2(g2x, ib.x, xA45);
                xA67 = ffma2(g2x, ib.y, xA67);
                xA8  = fmaf(gx, i8, xA8);
                yA01 = ffma2(g2y, ia.x, yA01);
                yA23 = ffma2(g2y, ia.y, yA23);
                yA45 = ffma2(g2y, ib.x, yA45);
                yA67 = ffma2(g2y, ib.y, yA67);
                yA8  = fmaf(gy, i8, yA8);
            }
            ulonglong2 w;
            w.x = xA01; w.y = xA23; *(ulonglong2*)&s_fA[vI][bW][c0]     = w;
            w.x = yA01; w.y = yA23; *(ulonglong2*)&s_fA[vI][bW][c0 + 1] = w;
            w.x = xA45; w.y = xA67; *(ulonglong2*)&s_fB[vI][bW][c0]     = w;
            w.x = yA45; w.y = yA67; *(ulonglong2*)&s_fB[vI][bW][c0 + 1] = w;
            *(float2*)&s_f8[vI][bW][c0] = make_float2(xA8, yA8);
        }

        // ---- prefetch metadata for next group into buf p^1 ----
        const int gn = g + gridDim.x;
        if (gn < NGRP) {
            const int pn  = p ^ 1;
            const int v0n = gn * VB;
            if (t < VB * KNB) {
                const int vl = t / KNB, k = t - KNB * vl;
                const int vg = v0n + vl;
                s_idx[pn][vl][k] = (vg < V_TOT) ? nbr[(size_t)vg * KNB + k] : 0;
            }
#pragma unroll
            for (int e = t; e < VB * KNB * KNB; e += 256) {
                const int vl  = e / 81;
                const int rem = e - 81 * vl;
                const int vg  = v0n + vl;
                s_itp[pn][vl][rem / KNB][rem % KNB] =
                    (vg < V_TOT) ? itp[(size_t)vg * 81 + rem] : 0.0f;
            }
        }
        __syncthreads();  // B: s_f ready; also orders prev stage-3 s_red reads

        // ---- stage 2: conv. Weights reloaded each group (L1-hit after the
        //      first iteration; may-alias with `out` keeps them un-hoisted,
        //      so their registers are free during stage 1). ----
        ull Wk2[4][4];
        ull W8p[2];
#pragma unroll
        for (int kp = 0; kp < 4; kp++)
#pragma unroll
            for (int ci = 0; ci < 4; ci++)
                Wk2[ci][kp] = wbase2[(kp * 4 + ci) * 32];
        W8p[0] = wbase8[0];
        W8p[1] = wbase8[32];

#pragma unroll
        for (int v = 0; v < VB; v++) {
#pragma unroll
            for (int b = 0; b < NBS; b++) {
                const ulonglong2* pA = (const ulonglong2*)&s_fA[v][b][cg * 4];
                const ulonglong2* pB = (const ulonglong2*)&s_fB[v][b][cg * 4];
                ull a0 = 0, a1 = 0, a2 = 0, a3 = 0, a8 = 0;
#pragma unroll
                for (int ci = 0; ci < 4; ci++) {
                    const ulonglong2 fa = pA[ci];
                    const ulonglong2 fb = pB[ci];
                    a0 = ffma2(fa.x, Wk2[ci][0], a0);
                    a1 = ffma2(fa.y, Wk2[ci][1], a1);
                    a2 = ffma2(fb.x, Wk2[ci][2], a2);
                    a3 = ffma2(fb.y, Wk2[ci][3], a3);
                }
                const ulonglong2 f8p = *(const ulonglong2*)&s_f8[v][b][cg * 4];
                a8 = ffma2(f8p.x, W8p[0], a8);
                a8 = ffma2(f8p.y, W8p[1], a8);

                ull sp = fadd2(fadd2(a0, a1), fadd2(a2, a3));
                sp = fadd2(sp, a8);
                const float2 sf = unpack2(sp);
                s_red[cg][v][b][o] = sf.x + sf.y;
            }
        }
        __syncthreads();  // C: s_red ready

        // ---- stage 3: reduce 8 cgroups, bias, mask, coalesced store ----
#pragma unroll
        for (int r = 0; r < 2; r++) {
            const int b = b3 + r * 2;
            float s = 0.0f;
#pragma unroll
            for (int w8 = 0; w8 < 8; w8++)
                s += s_red[w8][vl3][b][oo3];
            s = (s + bias3) * (float)s_nz[p][vl3][b];
            const int vg = v0 + vl3;
            if (vg < V_TOT)
                out[((size_t)b * NCO + oo3) * V_TOT + vg] = s;
        }

        p ^= 1;
    }
}

extern "C" void kernel_launch(void* const* d_in, const int* in_sizes, int n_in,
                              void* d_out, int out_size) {
    (void)in_sizes; (void)n_in; (void)out_size;
    const float* x      = (const float*)d_in[0];
    const int*   nbr    = (const int*)  d_in[1];
    const float* itp    = (const float*)d_in[2];
    const float* conv_w = (const float*)d_in[3];
    const float* conv_b = (const float*)d_in[4];
    float*       out    = (float*)d_out;

    // 4096 threads: one per g_w2 entry
    wprep_kernel<<<16, 256>>>(conv_w);

    dim3 tb(32, 8);
    dim3 tg((V_TOT + 31) / 32, NROWS / 32);
    transpose_kernel<<<tg, tb>>>(x);

    // 444 = 3 CTAs x 148 SMs: fully-resident persistent grid
    sphere_kernel<<<444, 256>>>(nbr, itp, conv_b, out);
}